// round 5
// baseline (speedup 1.0000x reference)
#include <cuda_runtime.h>
#include <math.h>

#define BB   8
#define SS   128
#define HID  256
#define NH   4
#define DH   64
#define FF   1024
#define MM   (BB*SS)        // 1024 rows
#define PSTR 1280           // proj buffer row stride: q|k|v|aq|ak

// ---------------- scratch ----------------------------------------------------
__device__ float g_proj[MM * PSTR];
__device__ float g_ctx [MM * HID];
__device__ float g_h   [MM * HID];
__device__ float g_part[8 * MM * HID]; // split-K partials (8*MM*HID == 2*MM*FF)
__device__ float g_ff  [MM * FF];
__device__ float g_wf  [HID * 512];
__device__ float g_bf  [512];

// ---------------- f32x2 packed helpers ---------------------------------------
typedef unsigned long long u64;

__device__ __forceinline__ u64 ffma2(u64 a, u64 b, u64 c)
{
    u64 d;
    asm("fma.rn.f32x2 %0,%1,%2,%3;" : "=l"(d) : "l"(a), "l"(b), "l"(c));
    return d;
}
__device__ __forceinline__ void upk2(u64 v, float& lo, float& hi)
{
    asm("mov.b64 {%0,%1},%2;" : "=f"(lo), "=f"(hi) : "l"(v));
}

// =============================================================================
// GEMM body: 128 threads, BM=64, BN=64, BK=16, per-thread 8x4 via f32x2.
// A smem k-major (m-consecutive -> natural (m,m+1) pairs from LDS.128).
// B smem pair-duplicated ((b,b) pairs direct from LDS.128, no packing MOVs).
// Inner loop per kk: 4x LDS.128 + 16x FFMA2 = 64 FLOP.
// acc2[p][j] packs rows (ty*8+2p, ty*8+2p+1) at col tx*4+j.
// =============================================================================
__device__ __forceinline__ void gemm_body128(const float* __restrict__ A, int lda,
                                             const float* __restrict__ B, int ldb,
                                             int row0, int bcol0, int K,
                                             u64 acc2[4][4])
{
    __shared__ float As[16][68];     // [k][m]
    __shared__ float Bs[16][128];    // [k][2n] duplicated pairs

    const int tid = threadIdx.x;     // 128
    const int tx = tid & 15;
    const int ty = tid >> 4;

    const int ar0 = tid >> 2;        // 0..31
    const int ar1 = ar0 + 32;
    const int ac  = (tid & 3) << 2;
    const int br0 = tid >> 4;        // 0..7
    const int br1 = br0 + 8;
    const int bc  = (tid & 15) << 2;

    const float* Ap0 = A + (size_t)(row0 + ar0) * lda + ac;
    const float* Ap1 = A + (size_t)(row0 + ar1) * lda + ac;
    const float* Bp0 = B + (size_t)br0 * ldb + bcol0 + bc;
    const float* Bp1 = B + (size_t)br1 * ldb + bcol0 + bc;

    float4 aR0 = *(const float4*)Ap0;
    float4 aR1 = *(const float4*)Ap1;
    float4 bR0 = *(const float4*)Bp0;
    float4 bR1 = *(const float4*)Bp1;

#pragma unroll
    for (int p = 0; p < 4; p++)
#pragma unroll
        for (int j = 0; j < 4; j++) acc2[p][j] = 0ULL;

    for (int k0 = 0; k0 < K; k0 += 16) {
        __syncthreads();
        As[ac + 0][ar0] = aR0.x; As[ac + 1][ar0] = aR0.y;
        As[ac + 2][ar0] = aR0.z; As[ac + 3][ar0] = aR0.w;
        As[ac + 0][ar1] = aR1.x; As[ac + 1][ar1] = aR1.y;
        As[ac + 2][ar1] = aR1.z; As[ac + 3][ar1] = aR1.w;
        *(float4*)&Bs[br0][(bc << 1) + 0] = make_float4(bR0.x, bR0.x, bR0.y, bR0.y);
        *(float4*)&Bs[br0][(bc << 1) + 4] = make_float4(bR0.z, bR0.z, bR0.w, bR0.w);
        *(float4*)&Bs[br1][(bc << 1) + 0] = make_float4(bR1.x, bR1.x, bR1.y, bR1.y);
        *(float4*)&Bs[br1][(bc << 1) + 4] = make_float4(bR1.z, bR1.z, bR1.w, bR1.w);
        __syncthreads();

        if (k0 + 16 < K) {
            aR0 = *(const float4*)(Ap0 + k0 + 16);
            aR1 = *(const float4*)(Ap1 + k0 + 16);
            bR0 = *(const float4*)(Bp0 + (size_t)(k0 + 16) * ldb);
            bR1 = *(const float4*)(Bp1 + (size_t)(k0 + 16) * ldb);
        }

#pragma unroll
        for (int kk = 0; kk < 16; kk++) {
            ulonglong2 a01 = *(const ulonglong2*)&As[kk][ty << 3];
            ulonglong2 a23 = *(const ulonglong2*)&As[kk][(ty << 3) + 4];
            ulonglong2 b01 = *(const ulonglong2*)&Bs[kk][tx << 3];
            ulonglong2 b23 = *(const ulonglong2*)&Bs[kk][(tx << 3) + 4];
            u64 ap[4] = {a01.x, a01.y, a23.x, a23.y};
            u64 bp[4] = {b01.x, b01.y, b23.x, b23.y};
#pragma unroll
            for (int p = 0; p < 4; p++) {
                acc2[p][0] = ffma2(ap[p], bp[0], acc2[p][0]);
                acc2[p][1] = ffma2(ap[p], bp[1], acc2[p][1]);
                acc2[p][2] = ffma2(ap[p], bp[2], acc2[p][2]);
                acc2[p][3] = ffma2(ap[p], bp[3], acc2[p][3]);
            }
        }
    }
}

// =============================================================================
// fusew: Wf[:,0:256]=Wq@AWq, Wf[:,256:512]=Wk@AWk, fused biases. grid (8,5).
// =============================================================================
__global__ __launch_bounds__(128)
void fusew_kernel(const float* __restrict__ Wq, const float* __restrict__ bq,
                  const float* __restrict__ Wk, const float* __restrict__ bk,
                  const float* __restrict__ AWq, const float* __restrict__ Abq,
                  const float* __restrict__ AWk, const float* __restrict__ Abk,
                  float* __restrict__ Wf, float* __restrict__ bf)
{
    const int seg = blockIdx.x >> 2;
    const int wcol0 = (blockIdx.x & 3) * 64;

    if (blockIdx.y == 4) {
        const float* bin = seg ? bk : bq;
        const float* AW  = seg ? AWk : AWq;
        const float* Ab  = seg ? Abk : Abq;
        __shared__ float red[128];
        int t = threadIdx.x;
        int c = t & 63, half = t >> 6;
        float s = 0.f;
        for (int d = half * 128; d < half * 128 + 128; d++)
            s += bin[d] * AW[(size_t)d * HID + wcol0 + c];
        red[t] = s;
        __syncthreads();
        if (half == 0)
            bf[seg * 256 + wcol0 + c] = red[c] + red[64 + c] + Ab[wcol0 + c];
        return;
    }

    const float* A = seg ? Wk : Wq;
    const float* B = seg ? AWk : AWq;
    const int row0 = blockIdx.y * 64;
    u64 acc2[4][4];
    gemm_body128(A, HID, B, HID, row0, wcol0, HID, acc2);

    const int tx = threadIdx.x & 15, ty = threadIdx.x >> 4;
#pragma unroll
    for (int p = 0; p < 4; p++) {
        int r = row0 + (ty << 3) + (p << 1);
#pragma unroll
        for (int j = 0; j < 4; j++) {
            float lo, hi;
            upk2(acc2[p][j], lo, hi);
            Wf[(size_t)r * 512 + seg * 256 + wcol0 + (tx << 2) + j] = lo;
            Wf[(size_t)(r + 1) * 512 + seg * 256 + wcol0 + (tx << 2) + j] = hi;
        }
    }
}

// =============================================================================
// proj: all 5 projections. grid (20,16).
// =============================================================================
__global__ __launch_bounds__(128)
void proj_kernel(const float* __restrict__ x,
                 const float* __restrict__ Wq, const float* __restrict__ bq,
                 const float* __restrict__ Wk, const float* __restrict__ bk,
                 const float* __restrict__ Wv, const float* __restrict__ bv,
                 const float* __restrict__ Wf, const float* __restrict__ bf,
                 float* __restrict__ P)
{
    const int seg = blockIdx.x >> 2;
    const int wcol0 = (blockIdx.x & 3) * 64;
    const int row0 = blockIdx.y * 64;

    const float* W; const float* bias; int ldb; int bcol;
    if      (seg == 0) { W = Wq; bias = bq;        ldb = HID; bcol = wcol0; }
    else if (seg == 1) { W = Wk; bias = bk;        ldb = HID; bcol = wcol0; }
    else if (seg == 2) { W = Wv; bias = bv;        ldb = HID; bcol = wcol0; }
    else if (seg == 3) { W = Wf; bias = bf;        ldb = 512; bcol = wcol0; }
    else               { W = Wf; bias = bf + 256;  ldb = 512; bcol = 256 + wcol0; }

    u64 acc2[4][4];
    gemm_body128(x, HID, W, ldb, row0, bcol, HID, acc2);

    const int tx = threadIdx.x & 15, ty = threadIdx.x >> 4;
    const int ocol0 = blockIdx.x * 64;
#pragma unroll
    for (int p = 0; p < 4; p++) {
        int r = row0 + (ty << 3) + (p << 1);
#pragma unroll
        for (int j = 0; j < 4; j++) {
            int c = (tx << 2) + j;
            float lo, hi;
            upk2(acc2[p][j], lo, hi);
            P[(size_t)r * PSTR + ocol0 + c] = lo + bias[wcol0 + c];
            P[(size_t)(r + 1) * PSTR + ocol0 + c] = hi + bias[wcol0 + c];
        }
    }
}

// =============================================================================
// Split-K partial GEMM. grid (N/64, M/64, NS). Cp[ks*MM*N + r*N + c].
// =============================================================================
template<int NS>
__global__ __launch_bounds__(128)
void gemm_partialN(const float* __restrict__ A, const float* __restrict__ B,
                   float* __restrict__ Cp, int N, int K)
{
    const int ks = blockIdx.z;
    const int Ks = K / NS;
    const int row0 = blockIdx.y * 64;
    const int col0 = blockIdx.x * 64;
    u64 acc2[4][4];
    gemm_body128(A + (size_t)ks * Ks, K, B + (size_t)ks * Ks * N, N, row0, col0, Ks, acc2);

    float* C = Cp + (size_t)ks * MM * N;
    const int tx = threadIdx.x & 15, ty = threadIdx.x >> 4;
#pragma unroll
    for (int p = 0; p < 4; p++) {
        int r = row0 + (ty << 3) + (p << 1);
#pragma unroll
        for (int j = 0; j < 4; j++) {
            int c = col0 + (tx << 2) + j;
            float lo, hi;
            upk2(acc2[p][j], lo, hi);
            C[(size_t)r * N + c] = lo;
            C[(size_t)(r + 1) * N + c] = hi;
        }
    }
}

// =============================================================================
// gelu over 2 partials + bias: ffb = gelu(p0+p1+b1). MM*FF elems, float4.
// =============================================================================
__global__ __launch_bounds__(256)
void gelu_kernel(const float* __restrict__ Cp, const float* __restrict__ bias,
                 float* __restrict__ out)
{
    size_t i = (size_t)blockIdx.x * 256 + threadIdx.x;   // float4 index
    float4 p0 = ((const float4*)Cp)[i];
    float4 p1 = ((const float4*)(Cp + (size_t)MM * FF))[i];
    int col = (int)((i << 2) & (FF - 1));
    float4 bb = *(const float4*)&bias[col];
    float4 v;
    v.x = p0.x + p1.x + bb.x; v.y = p0.y + p1.y + bb.y;
    v.z = p0.z + p1.z + bb.z; v.w = p0.w + p1.w + bb.w;
    const float c = 0.70710678118654752f;
    v.x = 0.5f * v.x * (1.0f + erff(v.x * c));
    v.y = 0.5f * v.y * (1.0f + erff(v.y * c));
    v.z = 0.5f * v.z * (1.0f + erff(v.z * c));
    v.w = 0.5f * v.w * (1.0f + erff(v.w * c));
    ((float4*)out)[i] = v;
}

// =============================================================================
// Fused attention (unchanged): 256 threads, 8 warps = 8 queries of one (b,h).
// =============================================================================
__device__ __forceinline__ void softmax4(const float x[4], float p[4])
{
    float m = fmaxf(fmaxf(x[0], x[1]), fmaxf(x[2], x[3]));
#pragma unroll
    for (int o = 16; o; o >>= 1) m = fmaxf(m, __shfl_xor_sync(0xffffffffu, m, o));
    float e0 = __expf(x[0] - m), e1 = __expf(x[1] - m);
    float e2 = __expf(x[2] - m), e3 = __expf(x[3] - m);
    float s = e0 + e1 + e2 + e3;
#pragma unroll
    for (int o = 16; o; o >>= 1) s += __shfl_xor_sync(0xffffffffu, s, o);
    float r = 1.f / s;
    p[0] = e0 * r; p[1] = e1 * r; p[2] = e2 * r; p[3] = e3 * r;
}

__global__ __launch_bounds__(256)
void attn_kernel(const float* __restrict__ P, const float* __restrict__ mask,
                 const float* __restrict__ order_w, const float* __restrict__ order_b,
                 const float* __restrict__ dist_w, const float* __restrict__ dist_b,
                 const float* __restrict__ scalar, float* __restrict__ ctx)
{
    __shared__ float tile[128][68];
    __shared__ float qsh[8][64];
    __shared__ float probs[8][128];
    __shared__ float kokd[128][2];
    __shared__ float wsh[256];

    const int tid = threadIdx.x;
    const int lane = tid & 31;
    const int w = tid >> 5;
    const int h = blockIdx.y, b = blockIdx.z;
    const int i0 = blockIdx.x * 8;
    const int i = i0 + w;

    const size_t rowbase = ((size_t)b * SS) * PSTR + h * DH;

#pragma unroll
    for (int f = tid; f < 128 * 16; f += 256) {
        int j = f >> 4, d4 = (f & 15) << 2;
        *(float4*)&tile[j][d4] = *(const float4*)&P[rowbase + (size_t)j * PSTR + 256 + d4];
    }
#pragma unroll
    for (int f = tid; f < 8 * 16; f += 256) {
        int r = f >> 4, d4 = (f & 15) << 2;
        *(float4*)&qsh[r][d4] = *(const float4*)&P[rowbase + (size_t)(i0 + r) * PSTR + d4];
    }
    wsh[tid] = (tid < 128) ? order_w[tid] : dist_w[tid - 128];
    __syncthreads();

    float s[4] = {0, 0, 0, 0};
#pragma unroll
    for (int d4 = 0; d4 < 64; d4 += 4) {
        float4 qv = *(const float4*)&qsh[w][d4];
#pragma unroll
        for (int jj = 0; jj < 4; jj++) {
            float4 kv = *(const float4*)&tile[lane + 32 * jj][d4];
            s[jj] = fmaf(qv.x, kv.x, fmaf(qv.y, kv.y, fmaf(qv.z, kv.z, fmaf(qv.w, kv.w, s[jj]))));
        }
    }
    if (tid < 128) {
        float ko = 0, kd = 0;
#pragma unroll
        for (int d4 = 0; d4 < 64; d4 += 4) {
            float4 kv = *(const float4*)&tile[tid][d4];
            float4 ov = *(const float4*)&wsh[64 + d4];
            float4 dv = *(const float4*)&wsh[192 + d4];
            ko = fmaf(kv.x, ov.x, fmaf(kv.y, ov.y, fmaf(kv.z, ov.z, fmaf(kv.w, ov.w, ko))));
            kd = fmaf(kv.x, dv.x, fmaf(kv.y, dv.y, fmaf(kv.z, dv.z, fmaf(kv.w, dv.w, kd))));
        }
        kokd[tid][0] = ko; kokd[tid][1] = kd;
    }
    float qo = qsh[w][lane] * wsh[lane] + qsh[w][lane + 32] * wsh[32 + lane];
    float qd = qsh[w][lane] * wsh[128 + lane] + qsh[w][lane + 32] * wsh[160 + lane];
#pragma unroll
    for (int o = 16; o; o >>= 1) {
        qo += __shfl_xor_sync(0xffffffffu, qo, o);
        qd += __shfl_xor_sync(0xffffffffu, qd, o);
    }
    __syncthreads();

#pragma unroll
    for (int f = tid; f < 128 * 16; f += 256) {
        int j = f >> 4, d4 = (f & 15) << 2;
        *(float4*)&tile[j][d4] = *(const float4*)&P[rowbase + (size_t)j * PSTR + 1024 + d4];
    }
#pragma unroll
    for (int f = tid; f < 8 * 16; f += 256) {
        int r = f >> 4, d4 = (f & 15) << 2;
        *(float4*)&qsh[r][d4] = *(const float4*)&P[rowbase + (size_t)(i0 + r) * PSTR + 768 + d4];
    }
    __syncthreads();

    float as[4] = {0, 0, 0, 0};
#pragma unroll
    for (int d4 = 0; d4 < 64; d4 += 4) {
        float4 qv = *(const float4*)&qsh[w][d4];
#pragma unroll
        for (int jj = 0; jj < 4; jj++) {
            float4 kv = *(const float4*)&tile[lane + 32 * jj][d4];
            as[jj] = fmaf(qv.x, kv.x, fmaf(qv.y, kv.y, fmaf(qv.z, kv.z, fmaf(qv.w, kv.w, as[jj]))));
        }
    }
    __syncthreads();

    float4 vreg[8];
#pragma unroll
    for (int t = 0; t < 8; t++) {
        int f = tid + t * 256;
        int j = f >> 4, d4 = (f & 15) << 2;
        vreg[t] = *(const float4*)&P[rowbase + (size_t)j * PSTR + 512 + d4];
    }

    const float ob = order_b[0], db = dist_b[0], sc = scalar[0];
    const float inv = 0.125f;
    float rich[4], orig[4], att[4];
#pragma unroll
    for (int jj = 0; jj < 4; jj++) {
        int j = lane + 32 * jj;
        float pr_o = 1.f / (1.f + __expf(-(qo + kokd[j][0] + ob)));
        float gd = (j > i) ? 1.f : 0.f;
        float err_o = __logf(pr_o + 1e-24f) * gd + __logf(1.f - pr_o + 1e-24f) * (1.f - gd);
        float gdd = __logf(fabsf((float)(j - i)) + 1.f);
        float diff = gdd - (qd + kokd[j][1] + db);
        float err_d = -0.5f * diff * diff * sc * sc;
        float mk = mask[((size_t)b * SS + i) * SS + j];
        rich[jj] = (s[jj] + err_o + err_d) * inv + mk;
        orig[jj] = s[jj] * inv + mk;
        att[jj]  = as[jj] * inv + mk;
    }
    float rich_p[4], orig_p[4], att_p[4], comb[4], comb_p[4], fin[4], fin_p[4];
    softmax4(rich, rich_p);
    softmax4(orig, orig_p);
    softmax4(att, att_p);
#pragma unroll
    for (int jj = 0; jj < 4; jj++) comb[jj] = orig_p[jj] + 0.5f * rich_p[jj];
    softmax4(comb, comb_p);
#pragma unroll
    for (int jj = 0; jj < 4; jj++) fin[jj] = comb_p[jj] + 0.5f * att_p[jj];
    softmax4(fin, fin_p);
#pragma unroll
    for (int jj = 0; jj < 4; jj++) probs[w][lane + 32 * jj] = fin_p[jj];

#pragma unroll
    for (int t = 0; t < 8; t++) {
        int f = tid + t * 256;
        int j = f >> 4, d4 = (f & 15) << 2;
        *(float4*)&tile[j][d4] = vreg[t];
    }
    __syncthreads();

    float c0 = 0.f, c1 = 0.f;
#pragma unroll 4
    for (int j = 0; j < 128; j++) {
        float p = probs[w][j];
        c0 = fmaf(p, tile[j][lane], c0);
        c1 = fmaf(p, tile[j][lane + 32], c1);
    }
    size_t obase = ((size_t)(b * SS + i)) * HID + h * DH;
    ctx[obase + lane] = c0;
    ctx[obase + lane + 32] = c1;
}

// =============================================================================
// LayerNorm over NP split-K partials + bias + residual.
// =============================================================================
template<int NP>
__global__ __launch_bounds__(256)
void ln_kernel(const float* __restrict__ Cp, const float* __restrict__ bias,
               const float* __restrict__ res, const float* __restrict__ g,
               const float* __restrict__ beta, float* __restrict__ out)
{
    int row = blockIdx.x;
    int t = threadIdx.x;
    int lane = t & 31, w = t >> 5;
    __shared__ float red[8];

    const size_t SZ = (size_t)MM * HID;
    size_t idx = (size_t)row * HID + t;
    float x = bias[t] + res[idx];
#pragma unroll
    for (int p = 0; p < NP; p++) x += Cp[p * SZ + idx];

    float v = x;
#pragma unroll
    for (int o = 16; o; o >>= 1) v += __shfl_xor_sync(0xffffffffu, v, o);
    if (lane == 0) red[w] = v;
    __syncthreads();
    float mean;
    {
        float r = (lane < 8) ? red[lane] : 0.f;
#pragma unroll
        for (int o = 4; o; o >>= 1) r += __shfl_xor_sync(0xffffffffu, r, o);
        mean = __shfl_sync(0xffffffffu, r, 0) * (1.0f / HID);
    }
    float d = x - mean;
    v = d * d;
#pragma unroll
    for (int o = 16; o; o >>= 1) v += __shfl_xor_sync(0xffffffffu, v, o);
    __syncthreads();
    if (lane == 0) red[w] = v;
    __syncthreads();
    float var;
    {
        float r = (lane < 8) ? red[lane] : 0.f;
#pragma unroll
        for (int o = 4; o; o >>= 1) r += __shfl_xor_sync(0xffffffffu, r, o);
        var = __shfl_sync(0xffffffffu, r, 0) * (1.0f / HID);
    }
    float invs = rsqrtf(var + 1e-12f);
    out[idx] = d * invs * g[t] + beta[t];
}

// ---------------- launch -----------------------------------------------------
extern "C" void kernel_launch(void* const* d_in, const int* in_sizes, int n_in,
                              void* d_out, int out_size)
{
    const float* x       = (const float*)d_in[0];
    const float* mask    = (const float*)d_in[1];
    const float* Wq      = (const float*)d_in[2];
    const float* bq      = (const float*)d_in[3];
    const float* Wk      = (const float*)d_in[4];
    const float* bk      = (const float*)d_in[5];
    const float* Wv      = (const float*)d_in[6];
    const float* bv      = (const float*)d_in[7];
    const float* order_w = (const float*)d_in[8];
    const float* order_b = (const float*)d_in[9];
    const float* dist_w  = (const float*)d_in[10];
    const float* dist_b  = (const float*)d_in[11];
    const float* scalar  = (const float*)d_in[12];
    const float* AWq     = (const float*)d_in[13];
    const float* Abq     = (const float*)d_in[14];
    const float* AWk     = (const float*)d_in[15];
    const float* Abk     = (const float*)d_in[16];
    const float* Wd      = (const float*)d_in[17];
    const float* bd      = (const float*)d_in[18];
    const float* g1      = (const float*)d_in[19];
    const float* beta1   = (const float*)d_in[20];
    const float* W1      = (const float*)d_in[21];
    const float* b1      = (const float*)d_in[22];
    const float* W2      = (const float*)d_in[23];
    const float* b2      = (const float*)d_in[24];
    const float* g2      = (const float*)d_in[25];
    const float* beta2   = (const float*)d_in[26];
    float* out = (float*)d_out;

    float *P, *ctx, *hbuf, *part, *ffb, *wf, *bf;
    cudaGetSymbolAddress((void**)&P,    g_proj);
    cudaGetSymbolAddress((void**)&ctx,  g_ctx);
    cudaGetSymbolAddress((void**)&hbuf, g_h);
    cudaGetSymbolAddress((void**)&part, g_part);
    cudaGetSymbolAddress((void**)&ffb,  g_ff);
    cudaGetSymbolAddress((void**)&wf,   g_wf);
    cudaGetSymbolAddress((void**)&bf,   g_bf);

    // fused attack weights/biases
    fusew_kernel<<<dim3(8, 5), 128>>>(Wq, bq, Wk, bk, AWq, Abq, AWk, Abk, wf, bf);

    // all 5 projections (320 blocks)
    proj_kernel<<<dim3(20, 16), 128>>>(x, Wq, bq, Wk, bk, Wv, bv, wf, bf, P);

    // fused attention (512 blocks)
    attn_kernel<<<dim3(SS / 8, NH, BB), 256>>>(P, mask, order_w, order_b,
                                               dist_w, dist_b, scalar, ctx);

    // output projection split-K=8 (512 blocks) + fused bias/res LN1
    gemm_partialN<8><<<dim3(4, 16, 8), 128>>>(ctx, Wd, part, HID, HID);
    ln_kernel<8><<<MM, 256>>>(part, bd, x, g1, beta1, hbuf);

    // FFN: W1 split-K=2 (512 blocks) -> gelu+sum -> W2 split-K=8 (512 blocks)
    gemm_partialN<2><<<dim3(16, 16, 2), 128>>>(hbuf, W1, part, FF, HID);
    gelu_kernel<<<(MM * FF / 4) / 256, 256>>>(part, b1, ffb);
    gemm_partialN<8><<<dim3(4, 16, 8), 128>>>(ffb, W2, part, HID, FF);
    ln_kernel<8><<<MM, 256>>>(part, b2, hbuf, g2, beta2, out);
}

// round 6
// speedup vs baseline: 1.7472x; 1.7472x over previous
#include <cuda_runtime.h>
#include <math.h>
#include <stdint.h>

#define BB   8
#define SS   128
#define HID  256
#define NH   4
#define DH   64
#define FF   1024
#define MM   (BB*SS)        // 1024 rows
#define PSTR 1280           // proj buffer row stride: q|k|v|aq|ak

// ---------------- scratch ----------------------------------------------------
__device__ float    g_P   [MM * PSTR];
__device__ float    g_h   [MM * HID];
__device__ float    g_part[8 * MM * HID];
__device__ float    g_bf  [512];

__device__ uint32_t g_tx  [MM * HID];
__device__ uint32_t g_tWq [HID * HID];
__device__ uint32_t g_tWk [HID * HID];
__device__ uint32_t g_tWv [HID * HID];
__device__ uint32_t g_tWd [HID * HID];
__device__ uint32_t g_tW1 [HID * FF];
__device__ uint32_t g_tW2 [FF * HID];
__device__ uint32_t g_twf [HID * 512];
__device__ uint32_t g_tctx[MM * HID];
__device__ uint32_t g_th  [MM * HID];
__device__ uint32_t g_tff [MM * FF];

// ---------------- helpers ------------------------------------------------------
__device__ __forceinline__ uint32_t f2t(float f)
{
    uint32_t r;
    asm("cvt.rna.tf32.f32 %0,%1;" : "=r"(r) : "f"(f));
    return r;
}

__device__ __forceinline__ void mma8(float* d,
                                     uint32_t a0, uint32_t a1, uint32_t a2, uint32_t a3,
                                     uint32_t b0, uint32_t b1)
{
    asm volatile(
        "mma.sync.aligned.m16n8k8.row.col.f32.tf32.tf32.f32 "
        "{%0,%1,%2,%3},{%4,%5,%6,%7},{%8,%9},{%0,%1,%2,%3};"
        : "+f"(d[0]), "+f"(d[1]), "+f"(d[2]), "+f"(d[3])
        : "r"(a0), "r"(a1), "r"(a2), "r"(a3), "r"(b0), "r"(b1));
}

// =============================================================================
// tf32 tensor-core GEMM body: 128 threads (4 warps), block tile 64x64, BK=16.
// A_t [M][K] tf32 row-major (lda), B_t [K][N] tf32 row-major (ldb).
// Warp w computes rows [w*16, w*16+16) x all 64 cols (8 n-tiles of m16n8k8).
// acc[t][0..3] per n-tile t, standard m16n8 C layout.
// =============================================================================
__device__ __forceinline__ void gemm_tf32(const uint32_t* __restrict__ A, int lda,
                                          const uint32_t* __restrict__ B, int ldb,
                                          int row0, int col0, int K,
                                          float acc[8][4])
{
    __shared__ uint32_t As[64][20];   // [m][k], pad 20 (conflict-free frag loads)
    __shared__ uint32_t Bs[16][68];   // [k][n], pad 68

    const int tid  = threadIdx.x;
    const int lane = tid & 31;
    const int w    = tid >> 5;
    const int g    = lane >> 2;       // groupID
    const int tig  = lane & 3;        // thread-in-group

    int ar[2], ac[2], br[2], bc[2];
#pragma unroll
    for (int u = 0; u < 2; u++) {
        int f = tid + 128 * u;        // 0..255 uint4 slots
        ar[u] = f >> 2;  ac[u] = (f & 3) << 2;    // A: 64x16
        br[u] = f >> 4;  bc[u] = (f & 15) << 2;   // B: 16x64
    }

    uint4 aR[2], bR[2];
#pragma unroll
    for (int u = 0; u < 2; u++) {
        aR[u] = *(const uint4*)&A[(size_t)(row0 + ar[u]) * lda + ac[u]];
        bR[u] = *(const uint4*)&B[(size_t)br[u] * ldb + col0 + bc[u]];
    }

#pragma unroll
    for (int t = 0; t < 8; t++)
#pragma unroll
        for (int j = 0; j < 4; j++) acc[t][j] = 0.f;

    for (int k0 = 0; k0 < K; k0 += 16) {
        __syncthreads();
#pragma unroll
        for (int u = 0; u < 2; u++) {
            *(uint4*)&As[ar[u]][ac[u]] = aR[u];
            *(uint4*)&Bs[br[u]][bc[u]] = bR[u];
        }
        __syncthreads();

        if (k0 + 16 < K) {
#pragma unroll
            for (int u = 0; u < 2; u++) {
                aR[u] = *(const uint4*)&A[(size_t)(row0 + ar[u]) * lda + k0 + 16 + ac[u]];
                bR[u] = *(const uint4*)&B[(size_t)(k0 + 16 + br[u]) * ldb + col0 + bc[u]];
            }
        }

#pragma unroll
        for (int ks = 0; ks < 16; ks += 8) {
            uint32_t a0 = As[w * 16 + g][ks + tig];
            uint32_t a1 = As[w * 16 + g + 8][ks + tig];
            uint32_t a2 = As[w * 16 + g][ks + tig + 4];
            uint32_t a3 = As[w * 16 + g + 8][ks + tig + 4];
#pragma unroll
            for (int t = 0; t < 8; t++) {
                uint32_t b0 = Bs[ks + tig][t * 8 + g];
                uint32_t b1 = Bs[ks + tig + 4][t * 8 + g];
                mma8(acc[t], a0, a1, a2, a3, b0, b1);
            }
        }
    }
}

// row/col of acc element: r = row0 + w*16 + g (+8 for c2/c3), c = col0 + t*8 + tig*2

// =============================================================================
// conv: fp32 -> tf32 pre-conversion of x and all big weights. 1024 blocks x 256.
// =============================================================================
__global__ __launch_bounds__(256)
void conv_kernel(const float* __restrict__ x,  const float* __restrict__ Wq,
                 const float* __restrict__ Wk, const float* __restrict__ Wv,
                 const float* __restrict__ Wd, const float* __restrict__ W1,
                 const float* __restrict__ W2,
                 uint32_t* __restrict__ tx,  uint32_t* __restrict__ tWq,
                 uint32_t* __restrict__ tWk, uint32_t* __restrict__ tWv,
                 uint32_t* __restrict__ tWd, uint32_t* __restrict__ tW1,
                 uint32_t* __restrict__ tW2)
{
    int i = blockIdx.x * 256 + threadIdx.x;   // float4 index, total 262144
    const float* src; uint32_t* dst; int off;
    if      (i < 65536)  { src = x;  dst = tx;  off = i; }
    else if (i < 81920)  { src = Wq; dst = tWq; off = i - 65536; }
    else if (i < 98304)  { src = Wk; dst = tWk; off = i - 81920; }
    else if (i < 114688) { src = Wv; dst = tWv; off = i - 98304; }
    else if (i < 131072) { src = Wd; dst = tWd; off = i - 114688; }
    else if (i < 196608) { src = W1; dst = tW1; off = i - 131072; }
    else                 { src = W2; dst = tW2; off = i - 196608; }
    float4 v = ((const float4*)src)[off];
    ((uint4*)dst)[off] = make_uint4(f2t(v.x), f2t(v.y), f2t(v.z), f2t(v.w));
}

// =============================================================================
// scalar GEMM body (R4) — used only by tiny fusew kernel.
// =============================================================================
__device__ __forceinline__ void gemm_body_s(const float* __restrict__ A, int lda,
                                            const float* __restrict__ B, int ldb,
                                            int row0, int bcol0, int K,
                                            float acc[8][4])
{
    __shared__ float As[16][68];
    __shared__ float Bs[16][64];

    const int tid = threadIdx.x;
    const int tx = tid & 15;
    const int ty = tid >> 4;
    const int ar0 = tid >> 2, ar1 = ar0 + 32, ac = (tid & 3) << 2;
    const int br0 = tid >> 4, br1 = br0 + 8, bc = (tid & 15) << 2;

    const float* Ap0 = A + (size_t)(row0 + ar0) * lda + ac;
    const float* Ap1 = A + (size_t)(row0 + ar1) * lda + ac;
    const float* Bp0 = B + (size_t)br0 * ldb + bcol0 + bc;
    const float* Bp1 = B + (size_t)br1 * ldb + bcol0 + bc;

    float4 aR0 = *(const float4*)Ap0, aR1 = *(const float4*)Ap1;
    float4 bR0 = *(const float4*)Bp0, bR1 = *(const float4*)Bp1;

#pragma unroll
    for (int i = 0; i < 8; i++)
#pragma unroll
        for (int j = 0; j < 4; j++) acc[i][j] = 0.f;

    for (int k0 = 0; k0 < K; k0 += 16) {
        __syncthreads();
        As[ac + 0][ar0] = aR0.x; As[ac + 1][ar0] = aR0.y;
        As[ac + 2][ar0] = aR0.z; As[ac + 3][ar0] = aR0.w;
        As[ac + 0][ar1] = aR1.x; As[ac + 1][ar1] = aR1.y;
        As[ac + 2][ar1] = aR1.z; As[ac + 3][ar1] = aR1.w;
        *(float4*)&Bs[br0][bc] = bR0;
        *(float4*)&Bs[br1][bc] = bR1;
        __syncthreads();

        if (k0 + 16 < K) {
            aR0 = *(const float4*)(Ap0 + k0 + 16);
            aR1 = *(const float4*)(Ap1 + k0 + 16);
            bR0 = *(const float4*)(Bp0 + (size_t)(k0 + 16) * ldb);
            bR1 = *(const float4*)(Bp1 + (size_t)(k0 + 16) * ldb);
        }
#pragma unroll
        for (int kk = 0; kk < 16; kk++) {
            float4 a0 = *(const float4*)&As[kk][ty * 8];
            float4 a1 = *(const float4*)&As[kk][ty * 8 + 4];
            float4 b  = *(const float4*)&Bs[kk][tx << 2];
            float am[8] = {a0.x, a0.y, a0.z, a0.w, a1.x, a1.y, a1.z, a1.w};
#pragma unroll
            for (int i = 0; i < 8; i++) {
                acc[i][0] = fmaf(am[i], b.x, acc[i][0]);
                acc[i][1] = fmaf(am[i], b.y, acc[i][1]);
                acc[i][2] = fmaf(am[i], b.z, acc[i][2]);
                acc[i][3] = fmaf(am[i], b.w, acc[i][3]);
            }
        }
    }
}

// =============================================================================
// fusew: wf = [Wq@AWq | Wk@AWk] (tf32 out), bf fused biases. grid (8,5).
// =============================================================================
__global__ __launch_bounds__(128)
void fusew_kernel(const float* __restrict__ Wq, const float* __restrict__ bq,
                  const float* __restrict__ Wk, const float* __restrict__ bk,
                  const float* __restrict__ AWq, const float* __restrict__ Abq,
                  const float* __restrict__ AWk, const float* __restrict__ Abk,
                  uint32_t* __restrict__ wf, float* __restrict__ bf)
{
    const int seg = blockIdx.x >> 2;
    const int wcol0 = (blockIdx.x & 3) * 64;

    if (blockIdx.y == 4) {
        const float* bin = seg ? bk : bq;
        const float* AW  = seg ? AWk : AWq;
        const float* Ab  = seg ? Abk : Abq;
        __shared__ float red[128];
        int t = threadIdx.x;
        int c = t & 63, half = t >> 6;
        float s = 0.f;
        for (int d = half * 128; d < half * 128 + 128; d++)
            s += bin[d] * AW[(size_t)d * HID + wcol0 + c];
        red[t] = s;
        __syncthreads();
        if (half == 0)
            bf[seg * 256 + wcol0 + c] = red[c] + red[64 + c] + Ab[wcol0 + c];
        return;
    }

    const float* A = seg ? Wk : Wq;
    const float* B = seg ? AWk : AWq;
    const int row0 = blockIdx.y * 64;
    float acc[8][4];
    gemm_body_s(A, HID, B, HID, row0, wcol0, HID, acc);

    const int tx = threadIdx.x & 15, ty = threadIdx.x >> 4;
#pragma unroll
    for (int i = 0; i < 8; i++) {
        int r = row0 + ty * 8 + i;
#pragma unroll
        for (int j = 0; j < 4; j++)
            wf[(size_t)r * 512 + seg * 256 + wcol0 + (tx << 2) + j] = f2t(acc[i][j]);
    }
}

// =============================================================================
// proj (tf32): all 5 projections from tx. grid (20,16), 128 threads.
// =============================================================================
__global__ __launch_bounds__(128)
void proj_kernel(const uint32_t* __restrict__ tx,
                 const uint32_t* __restrict__ tWq, const float* __restrict__ bq,
                 const uint32_t* __restrict__ tWk, const float* __restrict__ bk,
                 const uint32_t* __restrict__ tWv, const float* __restrict__ bv,
                 const uint32_t* __restrict__ twf, const float* __restrict__ bf,
                 float* __restrict__ P)
{
    const int seg = blockIdx.x >> 2;
    const int wcol0 = (blockIdx.x & 3) * 64;
    const int row0 = blockIdx.y * 64;

    const uint32_t* W; const float* bias; int ldb; int bcol;
    if      (seg == 0) { W = tWq; bias = bq;        ldb = HID; bcol = wcol0; }
    else if (seg == 1) { W = tWk; bias = bk;        ldb = HID; bcol = wcol0; }
    else if (seg == 2) { W = tWv; bias = bv;        ldb = HID; bcol = wcol0; }
    else if (seg == 3) { W = twf; bias = bf;        ldb = 512; bcol = wcol0; }
    else               { W = twf; bias = bf + 256;  ldb = 512; bcol = 256 + wcol0; }

    float acc[8][4];
    gemm_tf32(tx, HID, W, ldb, row0, bcol, HID, acc);

    const int lane = threadIdx.x & 31, w = threadIdx.x >> 5;
    const int g = lane >> 2, tig = lane & 3;
    const int ocol0 = blockIdx.x * 64;
#pragma unroll
    for (int t = 0; t < 8; t++) {
        int c = t * 8 + tig * 2;
        int r = row0 + w * 16 + g;
        float b0 = bias[wcol0 + c], b1 = bias[wcol0 + c + 1];
        *(float2*)&P[(size_t)r * PSTR + ocol0 + c] =
            make_float2(acc[t][0] + b0, acc[t][1] + b1);
        *(float2*)&P[(size_t)(r + 8) * PSTR + ocol0 + c] =
            make_float2(acc[t][2] + b0, acc[t][3] + b1);
    }
}

// =============================================================================
// Split-K partial GEMM (tf32). grid (N/64, M/64, NS).
// =============================================================================
template<int NS>
__global__ __launch_bounds__(128)
void gemm_partial_t(const uint32_t* __restrict__ A, const uint32_t* __restrict__ B,
                    float* __restrict__ Cp, int N, int K)
{
    const int ks = blockIdx.z;
    const int Ks = K / NS;
    const int row0 = blockIdx.y * 64;
    const int col0 = blockIdx.x * 64;
    float acc[8][4];
    gemm_tf32(A + (size_t)ks * Ks, K, B + (size_t)ks * Ks * N, N, row0, col0, Ks, acc);

    float* C = Cp + (size_t)ks * MM * N;
    const int lane = threadIdx.x & 31, w = threadIdx.x >> 5;
    const int g = lane >> 2, tig = lane & 3;
#pragma unroll
    for (int t = 0; t < 8; t++) {
        int c = col0 + t * 8 + tig * 2;
        int r = row0 + w * 16 + g;
        *(float2*)&C[(size_t)r * N + c]       = make_float2(acc[t][0], acc[t][1]);
        *(float2*)&C[(size_t)(r + 8) * N + c] = make_float2(acc[t][2], acc[t][3]);
    }
}

// =============================================================================
// W1 (tf32): th @ tW1 + b1, gelu, write tf32 to tff. grid (16,16).
// =============================================================================
__global__ __launch_bounds__(128)
void gemm_w1(const uint32_t* __restrict__ A, const uint32_t* __restrict__ B,
             const float* __restrict__ bias, uint32_t* __restrict__ C)
{
    const int row0 = blockIdx.y * 64;
    const int col0 = blockIdx.x * 64;
    float acc[8][4];
    gemm_tf32(A, HID, B, FF, row0, col0, HID, acc);

    const int lane = threadIdx.x & 31, w = threadIdx.x >> 5;
    const int g = lane >> 2, tig = lane & 3;
    const float cg = 0.70710678118654752f;
#pragma unroll
    for (int t = 0; t < 8; t++) {
        int c = col0 + t * 8 + tig * 2;
        int r = row0 + w * 16 + g;
        float b0 = bias[c], b1 = bias[c + 1];
        float v00 = acc[t][0] + b0, v01 = acc[t][1] + b1;
        float v10 = acc[t][2] + b0, v11 = acc[t][3] + b1;
        v00 = 0.5f * v00 * (1.0f + erff(v00 * cg));
        v01 = 0.5f * v01 * (1.0f + erff(v01 * cg));
        v10 = 0.5f * v10 * (1.0f + erff(v10 * cg));
        v11 = 0.5f * v11 * (1.0f + erff(v11 * cg));
        C[(size_t)r * FF + c]           = f2t(v00);
        C[(size_t)r * FF + c + 1]       = f2t(v01);
        C[(size_t)(r + 8) * FF + c]     = f2t(v10);
        C[(size_t)(r + 8) * FF + c + 1] = f2t(v11);
    }
}

// =============================================================================
// Fused attention: 256 threads, 8 warps = 8 queries of one (b,h). Writes tf32 ctx.
// =============================================================================
__device__ __forceinline__ void softmax4(const float x[4], float p[4])
{
    float m = fmaxf(fmaxf(x[0], x[1]), fmaxf(x[2], x[3]));
#pragma unroll
    for (int o = 16; o; o >>= 1) m = fmaxf(m, __shfl_xor_sync(0xffffffffu, m, o));
    float e0 = __expf(x[0] - m), e1 = __expf(x[1] - m);
    float e2 = __expf(x[2] - m), e3 = __expf(x[3] - m);
    float s = e0 + e1 + e2 + e3;
#pragma unroll
    for (int o = 16; o; o >>= 1) s += __shfl_xor_sync(0xffffffffu, s, o);
    float r = 1.f / s;
    p[0] = e0 * r; p[1] = e1 * r; p[2] = e2 * r; p[3] = e3 * r;
}

__global__ __launch_bounds__(256)
void attn_kernel(const float* __restrict__ P, const float* __restrict__ mask,
                 const float* __restrict__ order_w, const float* __restrict__ order_b,
                 const float* __restrict__ dist_w, const float* __restrict__ dist_b,
                 const float* __restrict__ scalar, uint32_t* __restrict__ tctx)
{
    __shared__ float tile[128][68];
    __shared__ float qsh[8][64];
    __shared__ float probs[8][128];
    __shared__ float kokd[128][2];
    __shared__ float wsh[256];

    const int tid = threadIdx.x;
    const int lane = tid & 31;
    const int w = tid >> 5;
    const int h = blockIdx.y, b = blockIdx.z;
    const int i0 = blockIdx.x * 8;
    const int i = i0 + w;

    const size_t rowbase = ((size_t)b * SS) * PSTR + h * DH;

#pragma unroll
    for (int f = tid; f < 128 * 16; f += 256) {
        int j = f >> 4, d4 = (f & 15) << 2;
        *(float4*)&tile[j][d4] = *(const float4*)&P[rowbase + (size_t)j * PSTR + 256 + d4];
    }
#pragma unroll
    for (int f = tid; f < 8 * 16; f += 256) {
        int r = f >> 4, d4 = (f & 15) << 2;
        *(float4*)&qsh[r][d4] = *(const float4*)&P[rowbase + (size_t)(i0 + r) * PSTR + d4];
    }
    wsh[tid] = (tid < 128) ? order_w[tid] : dist_w[tid - 128];
    __syncthreads();

    float s[4] = {0, 0, 0, 0};
#pragma unroll
    for (int d4 = 0; d4 < 64; d4 += 4) {
        float4 qv = *(const float4*)&qsh[w][d4];
#pragma unroll
        for (int jj = 0; jj < 4; jj++) {
            float4 kv = *(const float4*)&tile[lane + 32 * jj][d4];
            s[jj] = fmaf(qv.x, kv.x, fmaf(qv.y, kv.y, fmaf(qv.z, kv.z, fmaf(qv.w, kv.w, s[jj]))));
        }
    }
    if (tid < 128) {
        float ko = 0, kd = 0;
#pragma unroll
        for (int d4 = 0; d4 < 64; d4 += 4) {
            float4 kv = *(const float4*)&tile[tid][d4];
            float4 ov = *(const float4*)&wsh[64 + d4];
            float4 dv = *(const float4*)&wsh[192 + d4];
            ko = fmaf(kv.x, ov.x, fmaf(kv.y, ov.y, fmaf(kv.z, ov.z, fmaf(kv.w, ov.w, ko))));
            kd = fmaf(kv.x, dv.x, fmaf(kv.y, dv.y, fmaf(kv.z, dv.z, fmaf(kv.w, dv.w, kd))));
        }
        kokd[tid][0] = ko; kokd[tid][1] = kd;
    }
    float qo = qsh[w][lane] * wsh[lane] + qsh[w][lane + 32] * wsh[32 + lane];
    float qd = qsh[w][lane] * wsh[128 + lane] + qsh[w][lane + 32] * wsh[160 + lane];
#pragma unroll
    for (int o = 16; o; o >>= 1) {
        qo += __shfl_xor_sync(0xffffffffu, qo, o);
        qd += __shfl_xor_sync(0xffffffffu, qd, o);
    }
    __syncthreads();

#pragma unroll
    for (int f = tid; f < 128 * 16; f += 256) {
        int j = f >> 4, d4 = (f & 15) << 2;
        *(float4*)&tile[j][d4] = *(const float4*)&P[rowbase + (size_t)j * PSTR + 1024 + d4];
    }
#pragma unroll
    for (int f = tid; f < 8 * 16; f += 256) {
        int r = f >> 4, d4 = (f & 15) << 2;
        *(float4*)&qsh[r][d4] = *(const float4*)&P[rowbase + (size_t)(i0 + r) * PSTR + 768 + d4];
    }
    __syncthreads();

    float as[4] = {0, 0, 0, 0};
#pragma unroll
    for (int d4 = 0; d4 < 64; d4 += 4) {
        float4 qv = *(const float4*)&qsh[w][d4];
#pragma unroll
        for (int jj = 0; jj < 4; jj++) {
            float4 kv = *(const float4*)&tile[lane + 32 * jj][d4];
            as[jj] = fmaf(qv.x, kv.x, fmaf(qv.y, kv.y, fmaf(qv.z, kv.z, fmaf(qv.w, kv.w, as[jj]))));
        }
    }
    __syncthreads();

    float4 vreg[8];
#pragma unroll
    for (int t = 0; t < 8; t++) {
        int f = tid + t * 256;
        int j = f >> 4, d4 = (f & 15) << 2;
        vreg[t] = *(const float4*)&P[rowbase + (size_t)j * PSTR + 512 + d4];
    }

    const float ob = order_b[0], db = dist_b[0], sc = scalar[0];
    const float inv = 0.125f;
    float rich[4], orig[4], att[4];
#pragma unroll
    for (int jj = 0; jj < 4; jj++) {
        int j = lane + 32 * jj;
        float pr_o = 1.f / (1.f + __expf(-(qo + kokd[j][0] + ob)));
        float gd = (j > i) ? 1.f : 0.f;
        float err_o = __logf(pr_o + 1e-24f) * gd + __logf(1.f - pr_o + 1e-24f) * (1.f - gd);
        float gdd = __logf(fabsf((float)(j - i)) + 1.f);
        float diff = gdd - (qd + kokd[j][1] + db);
        float err_d = -0.5f * diff * diff * sc * sc;
        float mk = mask[((size_t)b * SS + i) * SS + j];
        rich[jj] = (s[jj] + err_o + err_d) * inv + mk;
        orig[jj] = s[jj] * inv + mk;
        att[jj]  = as[jj] * inv + mk;
    }
    float rich_p[4], orig_p[4], att_p[4], comb[4], comb_p[4], fin[4], fin_p[4];
    softmax4(rich, rich_p);
    softmax4(orig, orig_p);
    softmax4(att, att_p);
#pragma unroll
    for (int jj = 0; jj < 4; jj++) comb[jj] = orig_p[jj] + 0.5f * rich_p[jj];
    softmax4(comb, comb_p);
#pragma unroll
    for (int jj = 0; jj < 4; jj++) fin[jj] = comb_p[jj] + 0.5f * att_p[jj];
    softmax4(fin, fin_p);
#pragma unroll
    for (int jj = 0; jj < 4; jj++) probs[w][lane + 32 * jj] = fin_p[jj];

#pragma unroll
    for (int t = 0; t < 8; t++) {
        int f = tid + t * 256;
        int j = f >> 4, d4 = (f & 15) << 2;
        *(float4*)&tile[j][d4] = vreg[t];
    }
    __syncthreads();

    float c0 = 0.f, c1 = 0.f;
#pragma unroll 4
    for (int j = 0; j < 128; j++) {
        float p = probs[w][j];
        c0 = fmaf(p, tile[j][lane], c0);
        c1 = fmaf(p, tile[j][lane + 32], c1);
    }
    size_t obase = ((size_t)(b * SS + i)) * HID + h * DH;
    tctx[obase + lane]      = f2t(c0);
    tctx[obase + lane + 32] = f2t(c1);
}

// =============================================================================
// LayerNorm over NP split-K partials + bias + residual. Optionally tf32 copy.
// =============================================================================
template<int NP, bool TOUT>
__global__ __launch_bounds__(256)
void ln_kernel(const float* __restrict__ Cp, const float* __restrict__ bias,
               const float* __restrict__ res, const float* __restrict__ g,
               const float* __restrict__ beta, float* __restrict__ out,
               uint32_t* __restrict__ tout)
{
    int row = blockIdx.x;
    int t = threadIdx.x;
    int lane = t & 31, w = t >> 5;
    __shared__ float red[8];

    const size_t SZ = (size_t)MM * HID;
    size_t idx = (size_t)row * HID + t;
    float x = bias[t] + res[idx];
#pragma unroll
    for (int p = 0; p < NP; p++) x += Cp[p * SZ + idx];

    float v = x;
#pragma unroll
    for (int o = 16; o; o >>= 1) v += __shfl_xor_sync(0xffffffffu, v, o);
    if (lane == 0) red[w] = v;
    __syncthreads();
    float mean;
    {
        float r = (lane < 8) ? red[lane] : 0.f;
#pragma unroll
        for (int o = 4; o; o >>= 1) r += __shfl_xor_sync(0xffffffffu, r, o);
        mean = __shfl_sync(0xffffffffu, r, 0) * (1.0f / HID);
    }
    float d = x - mean;
    v = d * d;
#pragma unroll
    for (int o = 16; o; o >>= 1) v += __shfl_xor_sync(0xffffffffu, v, o);
    __syncthreads();
    if (lane == 0) red[w] = v;
    __syncthreads();
    float var;
    {
        float r = (lane < 8) ? red[lane] : 0.f;
#pragma unroll
        for (int o = 4; o; o >>= 1) r += __shfl_xor_sync(0xffffffffu, r, o);
        var = __shfl_sync(0xffffffffu, r, 0) * (1.0f / HID);
    }
    float invs = rsqrtf(var + 1e-12f);
    float y = d * invs * g[t] + beta[t];
    out[idx] = y;
    if (TOUT) tout[idx] = f2t(y);
}

// ---------------- launch -----------------------------------------------------
extern "C" void kernel_launch(void* const* d_in, const int* in_sizes, int n_in,
                              void* d_out, int out_size)
{
    const float* x       = (const float*)d_in[0];
    const float* mask    = (const float*)d_in[1];
    const float* Wq      = (const float*)d_in[2];
    const float* bq      = (const float*)d_in[3];
    const float* Wk      = (const float*)d_in[4];
    const float* bk      = (const float*)d_in[5];
    const float* Wv      = (const float*)d_in[6];
    const float* bv      = (const float*)d_in[7];
    const float* order_w = (const float*)d_in[8];
    const float* order_b = (const float*)d_in[9];
    const float* dist_w  = (const float*)d_in[10];
    const float* dist_b  = (const float*)d_in[11];
    const float* scalar  = (const float*)d_in[12];
    const float* AWq     = (const float*)d_in[13];
    const float* Abq     = (const float*)d_in[14];
    const float* AWk     = (const float*)d_in[15];
    const float* Abk     = (const float*)d_in[16];
    const float* Wd      = (const float*)d_in[17];
    const float* bd      = (const float*)d_in[18];
    const float* g1      = (const float*)d_in[19];
    const float* beta1   = (const float*)d_in[20];
    const float* W1      = (const float*)d_in[21];
    const float* b1      = (const float*)d_in[22];
    const float* W2      = (const float*)d_in[23];
    const float* b2      = (const float*)d_in[24];
    const float* g2      = (const float*)d_in[25];
    const float* beta2   = (const float*)d_in[26];
    float* out = (float*)d_out;

    float *P, *hbuf, *part, *bf;
    uint32_t *tx, *tWq, *tWk, *tWv, *tWd, *tW1, *tW2, *twf, *tctx, *th, *tff;
    cudaGetSymbolAddress((void**)&P,    g_P);
    cudaGetSymbolAddress((void**)&hbuf, g_h);
    cudaGetSymbolAddress((void**)&part, g_part);
    cudaGetSymbolAddress((void**)&bf,   g_bf);
    cudaGetSymbolAddress((void**)&tx,   g_tx);
    cudaGetSymbolAddress((void**)&tWq,  g_tWq);
    cudaGetSymbolAddress((void**)&tWk,  g_tWk);
    cudaGetSymbolAddress((void**)&tWv,  g_tWv);
    cudaGetSymbolAddress((void**)&tWd,  g_tWd);
    cudaGetSymbolAddress((void**)&tW1,  g_tW1);
    cudaGetSymbolAddress((void**)&tW2,  g_tW2);
    cudaGetSymbolAddress((void**)&twf,  g_twf);
    cudaGetSymbolAddress((void**)&tctx, g_tctx);
    cudaGetSymbolAddress((void**)&th,   g_th);
    cudaGetSymbolAddress((void**)&tff,  g_tff);

    // fp32 -> tf32 pre-conversion (x + all big weights)
    conv_kernel<<<1024, 256>>>(x, Wq, Wk, Wv, Wd, W1, W2,
                               tx, tWq, tWk, tWv, tWd, tW1, tW2);

    // fused attack weights/biases (scalar, tiny) -> tf32
    fusew_kernel<<<dim3(8, 5), 128>>>(Wq, bq, Wk, bk, AWq, Abq, AWk, Abk, twf, bf);

    // all 5 projections, tensor cores (320 blocks)
    proj_kernel<<<dim3(20, 16), 128>>>(tx, tWq, bq, tWk, bk, tWv, bv, twf, bf, P);

    // fused attention (512 blocks) -> tf32 ctx
    attn_kernel<<<dim3(SS / 8, NH, BB), 256>>>(P, mask, order_w, order_b,
                                               dist_w, dist_b, scalar, tctx);

    // output projection split-K=4 + fused bias/res LN1 (writes fp32 + tf32)
    gemm_partial_t<4><<<dim3(4, 16, 4), 128>>>(tctx, tWd, part, HID, HID);
    ln_kernel<4, true><<<MM, 256>>>(part, bd, x, g1, beta1, hbuf, th);

    // FFN: W1 (bias+gelu -> tf32), W2 split-K=8, LN2
    gemm_w1<<<dim3(16, 16), 128>>>(th, tW1, b1, tff);
    gemm_partial_t<8><<<dim3(4, 16, 8), 128>>>(tff, tW2, part, HID, FF);
    ln_kernel<8, false><<<MM, 256>>>(part, b2, hbuf, g2, beta2, out, nullptr);
}

// round 7
// speedup vs baseline: 1.8764x; 1.0740x over previous
#include <cuda_runtime.h>
#include <math.h>
#include <stdint.h>

#define BB   8
#define SS   128
#define HID  256
#define NH   4
#define DH   64
#define FF   1024
#define MM   (BB*SS)        // 1024 rows
#define PSTR 1280           // proj buffer row stride: q|k|v|aq|ak

// ---------------- scratch ----------------------------------------------------
__device__ float    g_P   [MM * PSTR];
__device__ float    g_h   [MM * HID];
__device__ float    g_part[8 * MM * HID];
__device__ float    g_bf  [512];

__device__ uint32_t g_tx  [MM * HID];
__device__ uint32_t g_tWq [HID * HID];
__device__ uint32_t g_tWk [HID * HID];
__device__ uint32_t g_tWv [HID * HID];
__device__ uint32_t g_tWd [HID * HID];
__device__ uint32_t g_tW1 [HID * FF];
__device__ uint32_t g_tW2 [FF * HID];
__device__ uint32_t g_tAWq[HID * HID];
__device__ uint32_t g_tAWk[HID * HID];
__device__ uint32_t g_twf [HID * 512];
__device__ uint32_t g_tctx[MM * HID];
__device__ uint32_t g_th  [MM * HID];
__device__ uint32_t g_tff [MM * FF];

// ---------------- helpers ------------------------------------------------------
__device__ __forceinline__ uint32_t f2t(float f)
{
    uint32_t r;
    asm("cvt.rna.tf32.f32 %0,%1;" : "=r"(r) : "f"(f));
    return r;
}

__device__ __forceinline__ void mma8(float* d,
                                     uint32_t a0, uint32_t a1, uint32_t a2, uint32_t a3,
                                     uint32_t b0, uint32_t b1)
{
    asm volatile(
        "mma.sync.aligned.m16n8k8.row.col.f32.tf32.tf32.f32 "
        "{%0,%1,%2,%3},{%4,%5,%6,%7},{%8,%9},{%0,%1,%2,%3};"
        : "+f"(d[0]), "+f"(d[1]), "+f"(d[2]), "+f"(d[3])
        : "r"(a0), "r"(a1), "r"(a2), "r"(a3), "r"(b0), "r"(b1));
}

// =============================================================================
// tf32 tensor-core GEMM body: 128 threads (4 warps), block tile 64x64, BK=16.
// =============================================================================
__device__ __forceinline__ void gemm_tf32(const uint32_t* __restrict__ A, int lda,
                                          const uint32_t* __restrict__ B, int ldb,
                                          int row0, int col0, int K,
                                          float acc[8][4])
{
    __shared__ uint32_t As[64][20];
    __shared__ uint32_t Bs[16][68];

    const int tid  = threadIdx.x;
    const int lane = tid & 31;
    const int w    = tid >> 5;
    const int g    = lane >> 2;
    const int tig  = lane & 3;

    int ar[2], ac[2], br[2], bc[2];
#pragma unroll
    for (int u = 0; u < 2; u++) {
        int f = tid + 128 * u;
        ar[u] = f >> 2;  ac[u] = (f & 3) << 2;
        br[u] = f >> 4;  bc[u] = (f & 15) << 2;
    }

    uint4 aR[2], bR[2];
#pragma unroll
    for (int u = 0; u < 2; u++) {
        aR[u] = *(const uint4*)&A[(size_t)(row0 + ar[u]) * lda + ac[u]];
        bR[u] = *(const uint4*)&B[(size_t)br[u] * ldb + col0 + bc[u]];
    }

#pragma unroll
    for (int t = 0; t < 8; t++)
#pragma unroll
        for (int j = 0; j < 4; j++) acc[t][j] = 0.f;

    for (int k0 = 0; k0 < K; k0 += 16) {
        __syncthreads();
#pragma unroll
        for (int u = 0; u < 2; u++) {
            *(uint4*)&As[ar[u]][ac[u]] = aR[u];
            *(uint4*)&Bs[br[u]][bc[u]] = bR[u];
        }
        __syncthreads();

        if (k0 + 16 < K) {
#pragma unroll
            for (int u = 0; u < 2; u++) {
                aR[u] = *(const uint4*)&A[(size_t)(row0 + ar[u]) * lda + k0 + 16 + ac[u]];
                bR[u] = *(const uint4*)&B[(size_t)(k0 + 16 + br[u]) * ldb + col0 + bc[u]];
            }
        }

#pragma unroll
        for (int ks = 0; ks < 16; ks += 8) {
            uint32_t a0 = As[w * 16 + g][ks + tig];
            uint32_t a1 = As[w * 16 + g + 8][ks + tig];
            uint32_t a2 = As[w * 16 + g][ks + tig + 4];
            uint32_t a3 = As[w * 16 + g + 8][ks + tig + 4];
#pragma unroll
            for (int t = 0; t < 8; t++) {
                uint32_t b0 = Bs[ks + tig][t * 8 + g];
                uint32_t b1 = Bs[ks + tig + 4][t * 8 + g];
                mma8(acc[t], a0, a1, a2, a3, b0, b1);
            }
        }
    }
}

// =============================================================================
// conv: fp32 -> tf32 pre-conversion. 1152 blocks x 256 threads (float4 each).
// =============================================================================
__global__ __launch_bounds__(256)
void conv_kernel(const float* __restrict__ x,  const float* __restrict__ Wq,
                 const float* __restrict__ Wk, const float* __restrict__ Wv,
                 const float* __restrict__ Wd, const float* __restrict__ W1,
                 const float* __restrict__ W2, const float* __restrict__ AWq,
                 const float* __restrict__ AWk,
                 uint32_t* __restrict__ tx,  uint32_t* __restrict__ tWq,
                 uint32_t* __restrict__ tWk, uint32_t* __restrict__ tWv,
                 uint32_t* __restrict__ tWd, uint32_t* __restrict__ tW1,
                 uint32_t* __restrict__ tW2, uint32_t* __restrict__ tAWq,
                 uint32_t* __restrict__ tAWk)
{
    int i = blockIdx.x * 256 + threadIdx.x;   // float4 index, total 294912
    const float* src; uint32_t* dst; int off;
    if      (i < 65536)  { src = x;   dst = tx;   off = i; }
    else if (i < 81920)  { src = Wq;  dst = tWq;  off = i - 65536; }
    else if (i < 98304)  { src = Wk;  dst = tWk;  off = i - 81920; }
    else if (i < 114688) { src = Wv;  dst = tWv;  off = i - 98304; }
    else if (i < 131072) { src = Wd;  dst = tWd;  off = i - 114688; }
    else if (i < 196608) { src = W1;  dst = tW1;  off = i - 131072; }
    else if (i < 262144) { src = W2;  dst = tW2;  off = i - 196608; }
    else if (i < 278528) { src = AWq; dst = tAWq; off = i - 262144; }
    else                 { src = AWk; dst = tAWk; off = i - 278528; }
    float4 v = ((const float4*)src)[off];
    ((uint4*)dst)[off] = make_uint4(f2t(v.x), f2t(v.y), f2t(v.z), f2t(v.w));
}

// =============================================================================
// fusew (tf32): wf = [Wq@AWq | Wk@AWk], bf fused biases. grid (8,5).
// =============================================================================
__global__ __launch_bounds__(128)
void fusew_kernel(const uint32_t* __restrict__ tWq, const uint32_t* __restrict__ tWk,
                  const uint32_t* __restrict__ tAWq, const uint32_t* __restrict__ tAWk,
                  const float* __restrict__ bq,  const float* __restrict__ bk,
                  const float* __restrict__ AWq, const float* __restrict__ Abq,
                  const float* __restrict__ AWk, const float* __restrict__ Abk,
                  uint32_t* __restrict__ wf, float* __restrict__ bf)
{
    const int seg = blockIdx.x >> 2;
    const int wcol0 = (blockIdx.x & 3) * 64;

    if (blockIdx.y == 4) {
        const float* bin = seg ? bk : bq;
        const float* AW  = seg ? AWk : AWq;
        const float* Ab  = seg ? Abk : Abq;
        __shared__ float red[128];
        int t = threadIdx.x;
        int c = t & 63, half = t >> 6;
        float s = 0.f;
        for (int d = half * 128; d < half * 128 + 128; d++)
            s += bin[d] * AW[(size_t)d * HID + wcol0 + c];
        red[t] = s;
        __syncthreads();
        if (half == 0)
            bf[seg * 256 + wcol0 + c] = red[c] + red[64 + c] + Ab[wcol0 + c];
        return;
    }

    const uint32_t* A = seg ? tWk : tWq;
    const uint32_t* B = seg ? tAWk : tAWq;
    const int row0 = blockIdx.y * 64;
    float acc[8][4];
    gemm_tf32(A, HID, B, HID, row0, wcol0, HID, acc);

    const int lane = threadIdx.x & 31, w = threadIdx.x >> 5;
    const int g = lane >> 2, tig = lane & 3;
#pragma unroll
    for (int t = 0; t < 8; t++) {
        int c = seg * 256 + wcol0 + t * 8 + tig * 2;
        int r = row0 + w * 16 + g;
        wf[(size_t)r * 512 + c]           = f2t(acc[t][0]);
        wf[(size_t)r * 512 + c + 1]       = f2t(acc[t][1]);
        wf[(size_t)(r + 8) * 512 + c]     = f2t(acc[t][2]);
        wf[(size_t)(r + 8) * 512 + c + 1] = f2t(acc[t][3]);
    }
}

// =============================================================================
// proj (tf32): all 5 projections from tx. grid (20,16), 128 threads.
// =============================================================================
__global__ __launch_bounds__(128)
void proj_kernel(const uint32_t* __restrict__ tx,
                 const uint32_t* __restrict__ tWq, const float* __restrict__ bq,
                 const uint32_t* __restrict__ tWk, const float* __restrict__ bk,
                 const uint32_t* __restrict__ tWv, const float* __restrict__ bv,
                 const uint32_t* __restrict__ twf, const float* __restrict__ bf,
                 float* __restrict__ P)
{
    const int seg = blockIdx.x >> 2;
    const int wcol0 = (blockIdx.x & 3) * 64;
    const int row0 = blockIdx.y * 64;

    const uint32_t* W; const float* bias; int ldb; int bcol;
    if      (seg == 0) { W = tWq; bias = bq;        ldb = HID; bcol = wcol0; }
    else if (seg == 1) { W = tWk; bias = bk;        ldb = HID; bcol = wcol0; }
    else if (seg == 2) { W = tWv; bias = bv;        ldb = HID; bcol = wcol0; }
    else if (seg == 3) { W = twf; bias = bf;        ldb = 512; bcol = wcol0; }
    else               { W = twf; bias = bf + 256;  ldb = 512; bcol = 256 + wcol0; }

    float acc[8][4];
    gemm_tf32(tx, HID, W, ldb, row0, bcol, HID, acc);

    const int lane = threadIdx.x & 31, w = threadIdx.x >> 5;
    const int g = lane >> 2, tig = lane & 3;
    const int ocol0 = blockIdx.x * 64;
#pragma unroll
    for (int t = 0; t < 8; t++) {
        int c = t * 8 + tig * 2;
        int r = row0 + w * 16 + g;
        float b0 = bias[wcol0 + c], b1 = bias[wcol0 + c + 1];
        *(float2*)&P[(size_t)r * PSTR + ocol0 + c] =
            make_float2(acc[t][0] + b0, acc[t][1] + b1);
        *(float2*)&P[(size_t)(r + 8) * PSTR + ocol0 + c] =
            make_float2(acc[t][2] + b0, acc[t][3] + b1);
    }
}

// =============================================================================
// Split-K partial GEMM (tf32). grid (N/64, M/64, NS).
// =============================================================================
template<int NS>
__global__ __launch_bounds__(128)
void gemm_partial_t(const uint32_t* __restrict__ A, const uint32_t* __restrict__ B,
                    float* __restrict__ Cp, int N, int K)
{
    const int ks = blockIdx.z;
    const int Ks = K / NS;
    const int row0 = blockIdx.y * 64;
    const int col0 = blockIdx.x * 64;
    float acc[8][4];
    gemm_tf32(A + (size_t)ks * Ks, K, B + (size_t)ks * Ks * N, N, row0, col0, Ks, acc);

    float* C = Cp + (size_t)ks * MM * N;
    const int lane = threadIdx.x & 31, w = threadIdx.x >> 5;
    const int g = lane >> 2, tig = lane & 3;
#pragma unroll
    for (int t = 0; t < 8; t++) {
        int c = col0 + t * 8 + tig * 2;
        int r = row0 + w * 16 + g;
        *(float2*)&C[(size_t)r * N + c]       = make_float2(acc[t][0], acc[t][1]);
        *(float2*)&C[(size_t)(r + 8) * N + c] = make_float2(acc[t][2], acc[t][3]);
    }
}

// =============================================================================
// W1 (tf32): th @ tW1 + b1, gelu, write tf32. grid (16,16).
// =============================================================================
__global__ __launch_bounds__(128)
void gemm_w1(const uint32_t* __restrict__ A, const uint32_t* __restrict__ B,
             const float* __restrict__ bias, uint32_t* __restrict__ C)
{
    const int row0 = blockIdx.y * 64;
    const int col0 = blockIdx.x * 64;
    float acc[8][4];
    gemm_tf32(A, HID, B, FF, row0, col0, HID, acc);

    const int lane = threadIdx.x & 31, w = threadIdx.x >> 5;
    const int g = lane >> 2, tig = lane & 3;
    const float cg = 0.70710678118654752f;
#pragma unroll
    for (int t = 0; t < 8; t++) {
        int c = col0 + t * 8 + tig * 2;
        int r = row0 + w * 16 + g;
        float b0 = bias[c], b1 = bias[c + 1];
        float v00 = acc[t][0] + b0, v01 = acc[t][1] + b1;
        float v10 = acc[t][2] + b0, v11 = acc[t][3] + b1;
        v00 = 0.5f * v00 * (1.0f + erff(v00 * cg));
        v01 = 0.5f * v01 * (1.0f + erff(v01 * cg));
        v10 = 0.5f * v10 * (1.0f + erff(v10 * cg));
        v11 = 0.5f * v11 * (1.0f + erff(v11 * cg));
        C[(size_t)r * FF + c]           = f2t(v00);
        C[(size_t)r * FF + c + 1]       = f2t(v01);
        C[(size_t)(r + 8) * FF + c]     = f2t(v10);
        C[(size_t)(r + 8) * FF + c + 1] = f2t(v11);
    }
}

// =============================================================================
// Fused attention: 256 threads, 8 warps, 2 queries per warp (16/block).
// grid (SS/16, NH, BB) = 256 blocks. Static smem exactly 48KB.
// =============================================================================
__device__ __forceinline__ void softmax4(const float x[4], float p[4])
{
    float m = fmaxf(fmaxf(x[0], x[1]), fmaxf(x[2], x[3]));
#pragma unroll
    for (int o = 16; o; o >>= 1) m = fmaxf(m, __shfl_xor_sync(0xffffffffu, m, o));
    float e0 = __expf(x[0] - m), e1 = __expf(x[1] - m);
    float e2 = __expf(x[2] - m), e3 = __expf(x[3] - m);
    float s = e0 + e1 + e2 + e3;
#pragma unroll
    for (int o = 16; o; o >>= 1) s += __shfl_xor_sync(0xffffffffu, s, o);
    float r = __fdividef(1.f, s);
    p[0] = e0 * r; p[1] = e1 * r; p[2] = e2 * r; p[3] = e3 * r;
}

// chain of 5 softmaxes for one query; writes final probs
__device__ __forceinline__ void softmax_chain(const float s[4], const float as[4],
                                              const float erro[4], const float errd[4],
                                              const float mk[4], float* prow, int lane)
{
    const float inv = 0.125f;
    float rich[4], orig[4], att[4];
#pragma unroll
    for (int jj = 0; jj < 4; jj++) {
        rich[jj] = (s[jj] + erro[jj] + errd[jj]) * inv + mk[jj];
        orig[jj] = s[jj] * inv + mk[jj];
        att[jj]  = as[jj] * inv + mk[jj];
    }
    float rich_p[4], orig_p[4], att_p[4], comb[4], comb_p[4], fin[4], fin_p[4];
    softmax4(rich, rich_p);
    softmax4(orig, orig_p);
    softmax4(att, att_p);
#pragma unroll
    for (int jj = 0; jj < 4; jj++) comb[jj] = orig_p[jj] + 0.5f * rich_p[jj];
    softmax4(comb, comb_p);
#pragma unroll
    for (int jj = 0; jj < 4; jj++) fin[jj] = comb_p[jj] + 0.5f * att_p[jj];
    softmax4(fin, fin_p);
#pragma unroll
    for (int jj = 0; jj < 4; jj++) prow[lane + 32 * jj] = fin_p[jj];
}

__global__ __launch_bounds__(256)
void attn_kernel(const float* __restrict__ P, const float* __restrict__ mask,
                 const float* __restrict__ order_w, const float* __restrict__ order_b,
                 const float* __restrict__ dist_w, const float* __restrict__ dist_b,
                 const float* __restrict__ scalar, uint32_t* __restrict__ tctx)
{
    __shared__ float tile[128][68];     // k -> ak -> v
    __shared__ float qsh[16][64];       // q -> aq
    __shared__ float probs[16][128];
    __shared__ float kokd[128][2];
    __shared__ float wsh[256];          // order_w|dist_w, later gdd table

    const int tid = threadIdx.x;
    const int lane = tid & 31;
    const int w = tid >> 5;
    const int h = blockIdx.y, b = blockIdx.z;
    const int i0 = blockIdx.x * 16;
    const int ia = i0 + w;          // query A
    const int ib = i0 + w + 8;      // query B

    const size_t rowbase = ((size_t)b * SS) * PSTR + h * DH;

    // ---- phase 1: k tile + q rows + weights
#pragma unroll
    for (int f = tid; f < 128 * 16; f += 256) {
        int j = f >> 4, d4 = (f & 15) << 2;
        *(float4*)&tile[j][d4] = *(const float4*)&P[rowbase + (size_t)j * PSTR + 256 + d4];
    }
    {
        int r = tid >> 4, d4 = (tid & 15) << 2;
        *(float4*)&qsh[r][d4] = *(const float4*)&P[rowbase + (size_t)(i0 + r) * PSTR + d4];
    }
    wsh[tid] = (tid < 128) ? order_w[tid] : dist_w[tid - 128];
    __syncthreads();

    // scores q.k for both queries
    float sA[4] = {0, 0, 0, 0}, sB[4] = {0, 0, 0, 0};
#pragma unroll
    for (int d4 = 0; d4 < 64; d4 += 4) {
        float4 qa = *(const float4*)&qsh[w][d4];
        float4 qb = *(const float4*)&qsh[w + 8][d4];
#pragma unroll
        for (int jj = 0; jj < 4; jj++) {
            float4 kv = *(const float4*)&tile[lane + 32 * jj][d4];
            sA[jj] = fmaf(qa.x, kv.x, fmaf(qa.y, kv.y, fmaf(qa.z, kv.z, fmaf(qa.w, kv.w, sA[jj]))));
            sB[jj] = fmaf(qb.x, kv.x, fmaf(qb.y, kv.y, fmaf(qb.z, kv.z, fmaf(qb.w, kv.w, sB[jj]))));
        }
    }
    if (tid < 128) {
        float ko = 0, kd = 0;
#pragma unroll
        for (int d4 = 0; d4 < 64; d4 += 4) {
            float4 kv = *(const float4*)&tile[tid][d4];
            float4 ov = *(const float4*)&wsh[64 + d4];
            float4 dv = *(const float4*)&wsh[192 + d4];
            ko = fmaf(kv.x, ov.x, fmaf(kv.y, ov.y, fmaf(kv.z, ov.z, fmaf(kv.w, ov.w, ko))));
            kd = fmaf(kv.x, dv.x, fmaf(kv.y, dv.y, fmaf(kv.z, dv.z, fmaf(kv.w, dv.w, kd))));
        }
        kokd[tid][0] = ko; kokd[tid][1] = kd;
    }
    // per-query order/dist projections (both queries)
    float qoA = qsh[w][lane] * wsh[lane] + qsh[w][lane + 32] * wsh[32 + lane];
    float qdA = qsh[w][lane] * wsh[128 + lane] + qsh[w][lane + 32] * wsh[160 + lane];
    float qoB = qsh[w + 8][lane] * wsh[lane] + qsh[w + 8][lane + 32] * wsh[32 + lane];
    float qdB = qsh[w + 8][lane] * wsh[128 + lane] + qsh[w + 8][lane + 32] * wsh[160 + lane];
#pragma unroll
    for (int o = 16; o; o >>= 1) {
        qoA += __shfl_xor_sync(0xffffffffu, qoA, o);
        qdA += __shfl_xor_sync(0xffffffffu, qdA, o);
        qoB += __shfl_xor_sync(0xffffffffu, qoB, o);
        qdB += __shfl_xor_sync(0xffffffffu, qdB, o);
    }
    __syncthreads();

    // ---- phase 2: ak tile + aq rows; wsh becomes gdd table
#pragma unroll
    for (int f = tid; f < 128 * 16; f += 256) {
        int j = f >> 4, d4 = (f & 15) << 2;
        *(float4*)&tile[j][d4] = *(const float4*)&P[rowbase + (size_t)j * PSTR + 1024 + d4];
    }
    {
        int r = tid >> 4, d4 = (tid & 15) << 2;
        *(float4*)&qsh[r][d4] = *(const float4*)&P[rowbase + (size_t)(i0 + r) * PSTR + 768 + d4];
    }
    wsh[tid] = __logf(fabsf((float)(tid - 128)) + 1.0f);   // gdd(delta) at delta+128
    __syncthreads();

    float aA[4] = {0, 0, 0, 0}, aB[4] = {0, 0, 0, 0};
#pragma unroll
    for (int d4 = 0; d4 < 64; d4 += 4) {
        float4 qa = *(const float4*)&qsh[w][d4];
        float4 qb = *(const float4*)&qsh[w + 8][d4];
#pragma unroll
        for (int jj = 0; jj < 4; jj++) {
            float4 kv = *(const float4*)&tile[lane + 32 * jj][d4];
            aA[jj] = fmaf(qa.x, kv.x, fmaf(qa.y, kv.y, fmaf(qa.z, kv.z, fmaf(qa.w, kv.w, aA[jj]))));
            aB[jj] = fmaf(qb.x, kv.x, fmaf(qb.y, kv.y, fmaf(qb.z, kv.z, fmaf(qb.w, kv.w, aB[jj]))));
        }
    }
    __syncthreads();   // ak reads done; tile free for v

    // issue v loads (overlap with softmax math)
    float4 vreg[8];
#pragma unroll
    for (int t = 0; t < 8; t++) {
        int f = tid + t * 256;
        int j = f >> 4, d4 = (f & 15) << 2;
        vreg[t] = *(const float4*)&P[rowbase + (size_t)j * PSTR + 512 + d4];
    }

    // ---- error terms + 5 softmaxes per query
    const float ob = order_b[0], db = dist_b[0], sc = scalar[0];
    const float sc2h = 0.5f * sc * sc;
    float erro[4], errd[4], mk[4];

    // query A
#pragma unroll
    for (int jj = 0; jj < 4; jj++) {
        int j = lane + 32 * jj;
        float z = qoA + kokd[j][0] + ob;
        float sp = fmaxf(z, 0.f) + __logf(1.f + __expf(-fabsf(z)));   // softplus(z)
        erro[jj] = ((j > ia) ? z : 0.f) - sp;
        float diff = wsh[j - ia + 128] - (qdA + kokd[j][1] + db);
        errd[jj] = -diff * diff * sc2h;
        mk[jj] = mask[((size_t)b * SS + ia) * SS + j];
    }
    softmax_chain(sA, aA, erro, errd, mk, probs[w], lane);

    // query B
#pragma unroll
    for (int jj = 0; jj < 4; jj++) {
        int j = lane + 32 * jj;
        float z = qoB + kokd[j][0] + ob;
        float sp = fmaxf(z, 0.f) + __logf(1.f + __expf(-fabsf(z)));
        erro[jj] = ((j > ib) ? z : 0.f) - sp;
        float diff = wsh[j - ib + 128] - (qdB + kokd[j][1] + db);
        errd[jj] = -diff * diff * sc2h;
        mk[jj] = mask[((size_t)b * SS + ib) * SS + j];
    }
    softmax_chain(sB, aB, erro, errd, mk, probs[w + 8], lane);

    // commit v tile
#pragma unroll
    for (int t = 0; t < 8; t++) {
        int f = tid + t * 256;
        int j = f >> 4, d4 = (f & 15) << 2;
        *(float4*)&tile[j][d4] = vreg[t];
    }
    __syncthreads();

    // context for both queries
    float cA0 = 0.f, cA1 = 0.f, cB0 = 0.f, cB1 = 0.f;
#pragma unroll 4
    for (int j = 0; j < 128; j++) {
        float v0 = tile[j][lane], v1 = tile[j][lane + 32];
        float pa = probs[w][j], pb = probs[w + 8][j];
        cA0 = fmaf(pa, v0, cA0); cA1 = fmaf(pa, v1, cA1);
        cB0 = fmaf(pb, v0, cB0); cB1 = fmaf(pb, v1, cB1);
    }
    size_t oA = ((size_t)(b * SS + ia)) * HID + h * DH;
    size_t oB = ((size_t)(b * SS + ib)) * HID + h * DH;
    tctx[oA + lane]      = f2t(cA0);
    tctx[oA + lane + 32] = f2t(cA1);
    tctx[oB + lane]      = f2t(cB0);
    tctx[oB + lane + 32] = f2t(cB1);
}

// =============================================================================
// LayerNorm over NP split-K partials + bias + residual. Optional tf32 copy.
// =============================================================================
template<int NP, bool TOUT>
__global__ __launch_bounds__(256)
void ln_kernel(const float* __restrict__ Cp, const float* __restrict__ bias,
               const float* __restrict__ res, const float* __restrict__ g,
               const float* __restrict__ beta, float* __restrict__ out,
               uint32_t* __restrict__ tout)
{
    int row = blockIdx.x;
    int t = threadIdx.x;
    int lane = t & 31, w = t >> 5;
    __shared__ float red[8];

    const size_t SZ = (size_t)MM * HID;
    size_t idx = (size_t)row * HID + t;
    float x = bias[t] + res[idx];
#pragma unroll
    for (int p = 0; p < NP; p++) x += Cp[p * SZ + idx];

    float v = x;
#pragma unroll
    for (int o = 16; o; o >>= 1) v += __shfl_xor_sync(0xffffffffu, v, o);
    if (lane == 0) red[w] = v;
    __syncthreads();
    float mean;
    {
        float r = (lane < 8) ? red[lane] : 0.f;
#pragma unroll
        for (int o = 4; o; o >>= 1) r += __shfl_xor_sync(0xffffffffu, r, o);
        mean = __shfl_sync(0xffffffffu, r, 0) * (1.0f / HID);
    }
    float d = x - mean;
    v = d * d;
#pragma unroll
    for (int o = 16; o; o >>= 1) v += __shfl_xor_sync(0xffffffffu, v, o);
    __syncthreads();
    if (lane == 0) red[w] = v;
    __syncthreads();
    float var;
    {
        float r = (lane < 8) ? red[lane] : 0.f;
#pragma unroll
        for (int o = 4; o; o >>= 1) r += __shfl_xor_sync(0xffffffffu, r, o);
        var = __shfl_sync(0xffffffffu, r, 0) * (1.0f / HID);
    }
    float invs = rsqrtf(var + 1e-12f);
    float y = d * invs * g[t] + beta[t];
    out[idx] = y;
    if (TOUT) tout[idx] = f2t(y);
}

// ---------------- launch -----------------------------------------------------
extern "C" void kernel_launch(void* const* d_in, const int* in_sizes, int n_in,
                              void* d_out, int out_size)
{
    const float* x       = (const float*)d_in[0];
    const float* mask    = (const float*)d_in[1];
    const float* Wq      = (const float*)d_in[2];
    const float* bq      = (const float*)d_in[3];
    const float* Wk      = (const float*)d_in[4];
    const float* bk      = (const float*)d_in[5];
    const float* Wv      = (const float*)d_in[6];
    const float* bv      = (const float*)d_in[7];
    const float* order_w = (const float*)d_in[8];
    const float* order_b = (const float*)d_in[9];
    const float* dist_w  = (const float*)d_in[10];
    const float* dist_b  = (const float*)d_in[11];
    const float* scalar  = (const float*)d_in[12];
    const float* AWq     = (const float*)d_in[13];
    const float* Abq     = (const float*)d_in[14];
    const float* AWk     = (const float*)d_in[15];
    const float* Abk     = (const float*)d_in[16];
    const float* Wd      = (const float*)d_in[17];
    const float* bd      = (const float*)d_in[18];
    const float* g1      = (const float*)d_in[19];
    const float* beta1   = (const float*)d_in[20];
    const float* W1      = (const float*)d_in[21];
    const float* b1      = (const float*)d_in[22];
    const float* W2      = (const float*)d_in[23];
    const float* b2      = (const float*)d_in[24];
    const float* g2      = (const float*)d_in[25];
    const float* beta2   = (const float*)d_in[26];
    float* out = (float*)d_out;

    float *P, *hbuf, *part, *bf;
    uint32_t *tx, *tWq, *tWk, *tWv, *tWd, *tW1, *tW2, *tAWq, *tAWk, *twf, *tctx, *th, *tff;
    cudaGetSymbolAddress((void**)&P,    g_P);
    cudaGetSymbolAddress((void**)&hbuf, g_h);
    cudaGetSymbolAddress((void**)&part, g_part);
    cudaGetSymbolAddress((void**)&bf,   g_bf);
    cudaGetSymbolAddress((void**)&tx,   g_tx);
    cudaGetSymbolAddress((void**)&tWq,  g_tWq);
    cudaGetSymbolAddress((void**)&tWk,  g_tWk);
    cudaGetSymbolAddress((void**)&tWv,  g_tWv);
    cudaGetSymbolAddress((void**)&tWd,  g_tWd);
    cudaGetSymbolAddress((void**)&tW1,  g_tW1);
    cudaGetSymbolAddress((void**)&tW2,  g_tW2);
    cudaGetSymbolAddress((void**)&tAWq, g_tAWq);
    cudaGetSymbolAddress((void**)&tAWk, g_tAWk);
    cudaGetSymbolAddress((void**)&twf,  g_twf);
    cudaGetSymbolAddress((void**)&tctx, g_tctx);
    cudaGetSymbolAddress((void**)&th,   g_th);
    cudaGetSymbolAddress((void**)&tff,  g_tff);

    // fp32 -> tf32 pre-conversion
    conv_kernel<<<1152, 256>>>(x, Wq, Wk, Wv, Wd, W1, W2, AWq, AWk,
                               tx, tWq, tWk, tWv, tWd, tW1, tW2, tAWq, tAWk);

    // fused attack weights (tf32 mma) + biases
    fusew_kernel<<<dim3(8, 5), 128>>>(tWq, tWk, tAWq, tAWk,
                                      bq, bk, AWq, Abq, AWk, Abk, twf, bf);

    // all 5 projections, tensor cores (320 blocks)
    proj_kernel<<<dim3(20, 16), 128>>>(tx, tWq, bq, tWk, bk, tWv, bv, twf, bf, P);

    // fused attention (256 blocks, 2 queries/warp) -> tf32 ctx
    attn_kernel<<<dim3(SS / 16, NH, BB), 256>>>(P, mask, order_w, order_b,
                                                dist_w, dist_b, scalar, tctx);

    // output projection split-K=4 + fused bias/res LN1 (fp32 + tf32 out)
    gemm_partial_t<4><<<dim3(4, 16, 4), 128>>>(tctx, tWd, part, HID, HID);
    ln_kernel<4, true><<<MM, 256>>>(part, bd, x, g1, beta1, hbuf, th);

    // FFN
    gemm_w1<<<dim3(16, 16), 128>>>(th, tW1, b1, tff);
    gemm_partial_t<8><<<dim3(4, 16, 8), 128>>>(tff, tW2, part, HID, FF);
    ln_kernel<8, false><<<MM, 256>>>(part, b2, hbuf, g2, beta2, out, nullptr);
}